// round 6
// baseline (speedup 1.0000x reference)
#include <cuda_runtime.h>
#include <math.h>

#define F_CNT 1024
#define HH 192
#define WW 192
#define NPIX (HH*WW)
#define FXc 200.0f
#define FYc 200.0f
#define CXc 96.0f
#define CYc 96.0f
#define EPSf 1e-8f
#define SEG 8
#define GSEG 128                   // F_CNT / SEG
#define NRBLK 144                  // 12x12 tiles of 16x16 px

// ---------------- device scratch (no allocations allowed) ----------------
__device__ float4 g_sh1[F_CNT];    // sorted: mx, my, pA(=-.5*conA), pB(=-conB)
__device__ float  g_spC[F_CNT];    // sorted: pC(=-.5*conC)
__device__ float4 g_scold[F_CNT];  // sorted: opv, r, g, b
__device__ float  g_partial[NRBLK];
__device__ int    g_ready;         // 0-init; set by block 0, reset by last block
__device__ int    g_count;         // 0-init; ticket counter, reset by last block

__global__ void __launch_bounds__(1024, 1) fused_all_kernel(
        float* __restrict__ out,
        const float* __restrict__ img,
        const float* __restrict__ mask,
        const float* __restrict__ vp,
        const int*   __restrict__ faces,
        const float* __restrict__ qs,
        const float* __restrict__ ls,
        const float* __restrict__ cols,
        const float* __restrict__ lop)
{
    // 36 KB attr region, later aliased by comb (32 KB)
    __shared__ __align__(16) char smem_raw[36864];
    float4* sh1   = (float4*)smem_raw;                 // [1024]
    float*  spC   = (float*)(smem_raw + 16384);        // [1024]
    float4* scold = (float4*)(smem_raw + 20480);       // [1024]
    float4 (*comb)[256] = (float4(*)[256])smem_raw;    // [8][256] alias
    __shared__ unsigned long long sk[F_CNT];           // 8 KB (sort keys)
    __shared__ float red[256];
    __shared__ int s_last;

    int tid = threadIdx.x;

    // ================= block 0: preprocess + sort + publish =================
    if (blockIdx.x == 0) {
        int f = tid;
        int ia = faces[3*f+0], ib = faces[3*f+1], ic = faces[3*f+2];
        float ax = vp[3*ia], ay = vp[3*ia+1], az = vp[3*ia+2];
        float bx = vp[3*ib], by = vp[3*ib+1], bz = vp[3*ib+2];
        float cx = vp[3*ic], cy = vp[3*ic+1], cz = vp[3*ic+2];

        float tx = (ax+bx+cx)/3.0f, ty = (ay+by+cy)/3.0f, tz = (az+bz+cz)/3.0f;

        float e1x = bx-ax, e1y = by-ay, e1z = bz-az;
        float e2x = cx-ax, e2y = cy-ay, e2z = cz-az;
        float l1 = sqrtf(e1x*e1x + e1y*e1y + e1z*e1z);
        float i1 = 1.0f/(l1 + EPSf);
        float xx = e1x*i1, xy = e1y*i1, xz = e1z*i1;
        float nx = e1y*e2z - e1z*e2y;
        float ny = e1z*e2x - e1x*e2z;
        float nz = e1x*e2y - e1y*e2x;
        float ln = sqrtf(nx*nx + ny*ny + nz*nz);
        float in = 1.0f/(ln + EPSf);
        float zx = nx*in, zy = ny*in, zz = nz*in;
        float yx = zy*xz - zz*xy;
        float yy = zz*xx - zx*xz;
        float yz = zx*xy - zy*xx;

        float qw = qs[4*f+0], qx = qs[4*f+1], qy = qs[4*f+2], qz = qs[4*f+3];
        float qn = sqrtf(qw*qw + qx*qx + qy*qy + qz*qz);
        float iq = 1.0f/(qn + EPSf);
        qw *= iq; qx *= iq; qy *= iq; qz *= iq;
        float R00 = 1.0f - 2.0f*(qy*qy + qz*qz), R01 = 2.0f*(qx*qy - qw*qz), R02 = 2.0f*(qx*qz + qw*qy);
        float R10 = 2.0f*(qx*qy + qw*qz), R11 = 1.0f - 2.0f*(qx*qx + qz*qz), R12 = 2.0f*(qy*qz - qw*qx);
        float R20 = 2.0f*(qx*qz - qw*qy), R21 = 2.0f*(qy*qz + qw*qx), R22 = 1.0f - 2.0f*(qx*qx + qy*qy);

        float s0 = expf(ls[3*f+0]), s1 = expf(ls[3*f+1]), s2 = expf(ls[3*f+2]);

        float G[3][3];
        {
            float w0, w1, w2;
            w0 = R00*s0; w1 = R01*s1; w2 = R02*s2;
            G[0][0] = xx*w0 + yx*w1 + zx*w2;
            G[1][0] = xy*w0 + yy*w1 + zy*w2;
            G[2][0] = xz*w0 + yz*w1 + zz*w2;
            w0 = R10*s0; w1 = R11*s1; w2 = R12*s2;
            G[0][1] = xx*w0 + yx*w1 + zx*w2;
            G[1][1] = xy*w0 + yy*w1 + zy*w2;
            G[2][1] = xz*w0 + yz*w1 + zz*w2;
            w0 = R20*s0; w1 = R21*s1; w2 = R22*s2;
            G[0][2] = xx*w0 + yx*w1 + zx*w2;
            G[1][2] = xy*w0 + yy*w1 + zy*w2;
            G[2][2] = xz*w0 + yz*w1 + zz*w2;
        }

        float gs[3], Gr[3][3];
        #pragma unroll
        for (int j = 0; j < 3; j++) {
            gs[j] = sqrtf(G[0][j]*G[0][j] + G[1][j]*G[1][j] + G[2][j]*G[2][j]);
            float ig = 1.0f/(gs[j] + EPSf);
            Gr[0][j] = G[0][j]*ig; Gr[1][j] = G[1][j]*ig; Gr[2][j] = G[2][j]*ig;
        }

        float m00 = Gr[0][0], m11 = Gr[1][1], m22 = Gr[2][2];
        float pw = 0.5f*sqrtf(fmaxf(EPSf, 1.0f + m00 + m11 + m22));
        float px = 0.5f*sqrtf(fmaxf(EPSf, 1.0f + m00 - m11 - m22));
        float py = 0.5f*sqrtf(fmaxf(EPSf, 1.0f - m00 + m11 - m22));
        float pz = 0.5f*sqrtf(fmaxf(EPSf, 1.0f - m00 - m11 + m22));
        px = copysignf(px, Gr[2][1] - Gr[1][2]);
        py = copysignf(py, Gr[0][2] - Gr[2][0]);
        pz = copysignf(pz, Gr[1][0] - Gr[0][1]);

        float pn = sqrtf(pw*pw + px*px + py*py + pz*pz);
        float ip = 1.0f/(pn + EPSf);
        pw *= ip; px *= ip; py *= ip; pz *= ip;
        float N00 = 1.0f - 2.0f*(py*py + pz*pz), N01 = 2.0f*(px*py - pw*pz), N02 = 2.0f*(px*pz + pw*py);
        float N10 = 2.0f*(px*py + pw*pz), N11 = 1.0f - 2.0f*(px*px + pz*pz), N12 = 2.0f*(py*pz - pw*px);
        float N20 = 2.0f*(px*pz - pw*py), N21 = 2.0f*(py*pz + pw*px), N22 = 1.0f - 2.0f*(px*px + py*py);

        float M00 = N00*gs[0], M01 = N01*gs[1], M02 = N02*gs[2];
        float M10 = N10*gs[0], M11 = N11*gs[1], M12 = N12*gs[2];
        float M20 = N20*gs[0], M21 = N21*gs[1], M22 = N22*gs[2];
        float c300 = M00*M00 + M01*M01 + M02*M02;
        float c301 = M00*M10 + M01*M11 + M02*M12;
        float c302 = M00*M20 + M01*M21 + M02*M22;
        float c311 = M10*M10 + M11*M11 + M12*M12;
        float c312 = M10*M20 + M11*M21 + M12*M22;
        float c322 = M20*M20 + M21*M21 + M22*M22;

        float X = tx, Y = ty, Z = tz;
        float valid = (Z > 0.2f) ? 1.0f : 0.0f;
        float Zc = fmaxf(Z, 0.2f);
        float mx = FXc*X/Zc + CXc;
        float my = FYc*Y/Zc + CYc;
        float j00 = FXc/Zc;
        float j02 = -FXc*X/(Zc*Zc);
        float j11 = FYc/Zc;
        float j12 = -FYc*Y/(Zc*Zc);

        float u0 = j00*c300 + j02*c302;
        float u1 = j00*c301 + j02*c312;
        float u2 = j00*c302 + j02*c322;
        float v1 = j11*c311 + j12*c312;
        float v2 = j11*c312 + j12*c322;
        float cA = u0*j00 + u2*j02 + 0.3f;
        float cB = u1*j11 + u2*j12;
        float cC = v1*j11 + v2*j12 + 0.3f;
        float det = fmaxf(cA*cC - cB*cB, EPSf);
        float invd = 1.0f/det;

        sh1[f]   = make_float4(mx, my, -0.5f*cC*invd, cB*invd);
        spC[f]   = -0.5f*cA*invd;
        scold[f] = make_float4(expf(lop[f]) * valid, cols[3*f+0], cols[3*f+1], cols[3*f+2]);

        // stable bitonic sort on (Zc_bits << 32 | idx); Zc > 0 so float bits
        // are order-isomorphic as uint; idx makes it stable (== jnp.argsort).
        int t = f;
        unsigned long long key =
            ((unsigned long long)__float_as_uint(Zc) << 32) | (unsigned int)t;
        __syncthreads();

        #pragma unroll
        for (int k = 2; k <= F_CNT; k <<= 1) {
            bool dir = ((t & k) == 0);
            int j = k >> 1;
            for (; j >= 32; j >>= 1) {
                sk[t] = key;
                __syncthreads();
                unsigned long long other = sk[t ^ j];
                bool takeMin = (dir == ((t & j) == 0));
                key = ((key < other) == takeMin) ? key : other;
                __syncthreads();
            }
            for (; j >= 1; j >>= 1) {
                unsigned long long other = __shfl_xor_sync(0xffffffffu, key, j);
                bool takeMin = (dir == ((t & j) == 0));
                key = ((key < other) == takeMin) ? key : other;
            }
        }

        int s = (int)(key & 0xffffffffu);
        g_sh1[t]   = sh1[s];
        g_spC[t]   = spC[s];
        g_scold[t] = scold[s];
        __threadfence();
        __syncthreads();
        if (tid == 0) atomicExch(&g_ready, 1);
    } else {
        // wait for block 0's publish (all 144 blocks co-resident: grid <= #SMs)
        if (tid == 0) {
            while (atomicAdd(&g_ready, 0) == 0) __nanosleep(128);
        }
        __syncthreads();
        __threadfence();
    }

    // ================= render: 16x16 tile, 2 px/thread, 8 depth segs =================
    sh1[tid]   = g_sh1[tid];
    spC[tid]   = g_spC[tid];
    scold[tid] = g_scold[tid];
    __syncthreads();

    int pl  = tid & 127;          // pixel slot
    int seg = tid >> 7;           // depth segment
    int u = pl & 15;
    int v = pl >> 4;              // 0..7 ; second pixel at v+8
    int bx = blockIdx.x % 12, by = blockIdx.x / 12;
    float fx  = (float)(bx * 16 + u);
    float fy0 = (float)(by * 16 + v);
    float fy1 = fy0 + 8.0f;

    int base = seg * GSEG;
    float T0 = 1.0f, r0a = 0.0f, g0a = 0.0f, b0a = 0.0f;
    float T1 = 1.0f, r1a = 0.0f, g1a = 0.0f, b1a = 0.0f;
#pragma unroll 4
    for (int i = base; i < base + GSEG; i++) {
        float4 h = sh1[i];
        float pc = spC[i];
        float dx = fx - h.x;
        float q0 = h.z * dx * dx;       // shared: pA*dx^2
        float rb = h.w * dx;            // shared: pB*dx
        float dy0 = fy0 - h.y;
        float dy1 = fy1 - h.y;
        float p0 = fmaf(pc * dy0, dy0, fmaf(rb, dy0, q0));
        float p1 = fmaf(pc * dy1, dy1, fmaf(rb, dy1, q0));
        if (fmaxf(p0, p1) > -18.0f) {   // both alphas < 1.6e-8: skip
            float4 c = scold[i];
            float al0 = fminf(c.x * __expf(fminf(p0, 0.0f)), 0.99f);
            float al1 = fminf(c.x * __expf(fminf(p1, 0.0f)), 0.99f);
            float w0 = al0 * T0, w1 = al1 * T1;
            r0a = fmaf(w0, c.y, r0a);  r1a = fmaf(w1, c.y, r1a);
            g0a = fmaf(w0, c.z, g0a);  g1a = fmaf(w1, c.z, g1a);
            b0a = fmaf(w0, c.w, b0a);  b1a = fmaf(w1, c.w, b1a);
            T0 *= (1.0f - al0);        T1 *= (1.0f - al1);
        }
    }
    __syncthreads();                      // all smem reads done before comb aliases it
    comb[seg][pl]       = make_float4(T0, r0a, g0a, b0a);
    comb[seg][pl + 128] = make_float4(T1, r1a, g1a, b1a);
    __syncthreads();

    // ---- per-pixel ordered fold of 8 segments (threads 0..255) ----
    if (tid < 256) {
        float Tt = 1.0f, r = 0.0f, g = 0.0f, b = 0.0f;
#pragma unroll
        for (int s = 0; s < SEG; s++) {
            float4 vv = comb[s][tid];
            r = fmaf(Tt, vv.y, r);
            g = fmaf(Tt, vv.z, g);
            b = fmaf(Tt, vv.w, b);
            Tt *= vv.x;
        }
        float o0 = r + Tt, o1 = g + Tt, o2 = b + Tt;   // 1 - sum(w) == prod(1-alpha)
        // slot = pl + 128*pixhalf: pixhalf is BIT 7 of tid; row = (pl>>4) + 8*pixhalf
        int uu  = tid & 15;
        int vvi = ((tid >> 4) & 7) | ((tid >> 7) << 3); // 0..15
        int p = (by * 16 + vvi) * WW + (bx * 16 + uu);
        out[p]          = o0;
        out[NPIX + p]   = o1;
        out[2*NPIX + p] = o2;

        float m  = mask[p];
        float bt = 1.0f - m;
        float d0 = o0 - fmaf(img[p],          m, bt);
        float d1 = o1 - fmaf(img[NPIX + p],   m, bt);
        float d2 = o2 - fmaf(img[2*NPIX + p], m, bt);
        red[tid] = fmaf(d0, d0, fmaf(d1, d1, d2*d2));
    }
    __syncthreads();
#pragma unroll
    for (int s = 128; s > 0; s >>= 1) {
        if (tid < s) red[tid] += red[tid + s];
        __syncthreads();
    }

    // ---- last block finishes loss (fixed-order => deterministic) + resets state ----
    if (tid == 0) {
        g_partial[blockIdx.x] = red[0];
        __threadfence();
        int ticket = atomicAdd(&g_count, 1);
        s_last = (ticket == NRBLK - 1);
    }
    __syncthreads();
    if (s_last && tid < 32) {
        __threadfence();
        float a = 0.0f;
        for (int i = tid; i < NRBLK; i += 32)
            a += *((volatile float*)&g_partial[i]);
#pragma unroll
        for (int o = 16; o > 0; o >>= 1)
            a += __shfl_down_sync(0xffffffffu, a, o);
        if (tid == 0) {
            out[3 * NPIX] = a / (float)(3 * NPIX);
            g_count = 0;             // reset for next graph replay
            atomicExch(&g_ready, 0);
        }
    }
}

// ---------------- launch ----------------
extern "C" void kernel_launch(void* const* d_in, const int* in_sizes, int n_in,
                              void* d_out, int out_size)
{
    const float* img   = (const float*)d_in[0];
    const float* mask  = (const float*)d_in[1];
    const float* vp    = (const float*)d_in[2];
    const int*   faces = (const int*)  d_in[3];
    const float* qs    = (const float*)d_in[4];
    const float* ls    = (const float*)d_in[5];
    const float* cols  = (const float*)d_in[6];
    const float* lop   = (const float*)d_in[7];
    float* out = (float*)d_out;

    fused_all_kernel<<<NRBLK, 1024>>>(out, img, mask, vp, faces, qs, ls, cols, lop);
}

// round 7
// speedup vs baseline: 1.2320x; 1.2320x over previous
#include <cuda_runtime.h>
#include <math.h>

#define F_CNT 1024
#define HH 192
#define WW 192
#define NPIX (HH*WW)
#define FXc 200.0f
#define FYc 200.0f
#define CXc 96.0f
#define CYc 96.0f
#define EPSf 1e-8f
#define SEG 8
#define GSEG 128                   // F_CNT / SEG
#define NRBLK 288                  // render blocks: 288 x 128 px

// ---------------- device scratch (no allocations allowed) ----------------
__device__ float4 g_sh1[F_CNT];    // sorted: mx, my, pA(=-.5*conA), pB(=-conB)
__device__ float  g_spC[F_CNT];    // sorted: pC(=-.5*conC)
__device__ float4 g_scold[F_CNT];  // sorted: opv, r, g, b
__device__ float2 g_smyry[F_CNT];  // sorted: (my, ry=6*sqrt(cC))
__device__ float  g_partial[NRBLK];
__device__ int    g_count;         // 0-init; ticket counter, reset by last block

// ================= preprocess + stable sort, one block =================
__global__ void __launch_bounds__(1024) prep_sort_kernel(
        const float* __restrict__ vp,
        const int*   __restrict__ faces,
        const float* __restrict__ qs,
        const float* __restrict__ ls,
        const float* __restrict__ cols,
        const float* __restrict__ lop)
{
    __shared__ float4 h1s[F_CNT];
    __shared__ float  pCs[F_CNT];
    __shared__ float4 colds[F_CNT];
    __shared__ float  rys[F_CNT];
    __shared__ unsigned long long sk[F_CNT];

    int f = threadIdx.x;

    int ia = faces[3*f+0], ib = faces[3*f+1], ic = faces[3*f+2];
    float ax = vp[3*ia], ay = vp[3*ia+1], az = vp[3*ia+2];
    float bx = vp[3*ib], by = vp[3*ib+1], bz = vp[3*ib+2];
    float cx = vp[3*ic], cy = vp[3*ic+1], cz = vp[3*ic+2];

    float tx = (ax+bx+cx)/3.0f, ty = (ay+by+cy)/3.0f, tz = (az+bz+cz)/3.0f;

    float e1x = bx-ax, e1y = by-ay, e1z = bz-az;
    float e2x = cx-ax, e2y = cy-ay, e2z = cz-az;
    float l1 = sqrtf(e1x*e1x + e1y*e1y + e1z*e1z);
    float i1 = 1.0f/(l1 + EPSf);
    float xx = e1x*i1, xy = e1y*i1, xz = e1z*i1;
    float nx = e1y*e2z - e1z*e2y;
    float ny = e1z*e2x - e1x*e2z;
    float nz = e1x*e2y - e1y*e2x;
    float ln = sqrtf(nx*nx + ny*ny + nz*nz);
    float in = 1.0f/(ln + EPSf);
    float zx = nx*in, zy = ny*in, zz = nz*in;
    float yx = zy*xz - zz*xy;
    float yy = zz*xx - zx*xz;
    float yz = zx*xy - zy*xx;

    float qw = qs[4*f+0], qx = qs[4*f+1], qy = qs[4*f+2], qz = qs[4*f+3];
    float qn = sqrtf(qw*qw + qx*qx + qy*qy + qz*qz);
    float iq = 1.0f/(qn + EPSf);
    qw *= iq; qx *= iq; qy *= iq; qz *= iq;
    float R00 = 1.0f - 2.0f*(qy*qy + qz*qz), R01 = 2.0f*(qx*qy - qw*qz), R02 = 2.0f*(qx*qz + qw*qy);
    float R10 = 2.0f*(qx*qy + qw*qz), R11 = 1.0f - 2.0f*(qx*qx + qz*qz), R12 = 2.0f*(qy*qz - qw*qx);
    float R20 = 2.0f*(qx*qz - qw*qy), R21 = 2.0f*(qy*qz + qw*qx), R22 = 1.0f - 2.0f*(qx*qx + qy*qy);

    float s0 = expf(ls[3*f+0]), s1 = expf(ls[3*f+1]), s2 = expf(ls[3*f+2]);

    float G[3][3];
    {
        float w0, w1, w2;
        w0 = R00*s0; w1 = R01*s1; w2 = R02*s2;
        G[0][0] = xx*w0 + yx*w1 + zx*w2;
        G[1][0] = xy*w0 + yy*w1 + zy*w2;
        G[2][0] = xz*w0 + yz*w1 + zz*w2;
        w0 = R10*s0; w1 = R11*s1; w2 = R12*s2;
        G[0][1] = xx*w0 + yx*w1 + zx*w2;
        G[1][1] = xy*w0 + yy*w1 + zy*w2;
        G[2][1] = xz*w0 + yz*w1 + zz*w2;
        w0 = R20*s0; w1 = R21*s1; w2 = R22*s2;
        G[0][2] = xx*w0 + yx*w1 + zx*w2;
        G[1][2] = xy*w0 + yy*w1 + zy*w2;
        G[2][2] = xz*w0 + yz*w1 + zz*w2;
    }

    float gs[3], Gr[3][3];
    #pragma unroll
    for (int j = 0; j < 3; j++) {
        gs[j] = sqrtf(G[0][j]*G[0][j] + G[1][j]*G[1][j] + G[2][j]*G[2][j]);
        float ig = 1.0f/(gs[j] + EPSf);
        Gr[0][j] = G[0][j]*ig; Gr[1][j] = G[1][j]*ig; Gr[2][j] = G[2][j]*ig;
    }

    float m00 = Gr[0][0], m11 = Gr[1][1], m22 = Gr[2][2];
    float pw = 0.5f*sqrtf(fmaxf(EPSf, 1.0f + m00 + m11 + m22));
    float px = 0.5f*sqrtf(fmaxf(EPSf, 1.0f + m00 - m11 - m22));
    float py = 0.5f*sqrtf(fmaxf(EPSf, 1.0f - m00 + m11 - m22));
    float pz = 0.5f*sqrtf(fmaxf(EPSf, 1.0f - m00 - m11 + m22));
    px = copysignf(px, Gr[2][1] - Gr[1][2]);
    py = copysignf(py, Gr[0][2] - Gr[2][0]);
    pz = copysignf(pz, Gr[1][0] - Gr[0][1]);

    float pn = sqrtf(pw*pw + px*px + py*py + pz*pz);
    float ip = 1.0f/(pn + EPSf);
    pw *= ip; px *= ip; py *= ip; pz *= ip;
    float N00 = 1.0f - 2.0f*(py*py + pz*pz), N01 = 2.0f*(px*py - pw*pz), N02 = 2.0f*(px*pz + pw*py);
    float N10 = 2.0f*(px*py + pw*pz), N11 = 1.0f - 2.0f*(px*px + pz*pz), N12 = 2.0f*(py*pz - pw*px);
    float N20 = 2.0f*(px*pz - pw*py), N21 = 2.0f*(py*pz + pw*px), N22 = 1.0f - 2.0f*(px*px + py*py);

    float M00 = N00*gs[0], M01 = N01*gs[1], M02 = N02*gs[2];
    float M10 = N10*gs[0], M11 = N11*gs[1], M12 = N12*gs[2];
    float M20 = N20*gs[0], M21 = N21*gs[1], M22 = N22*gs[2];
    float c300 = M00*M00 + M01*M01 + M02*M02;
    float c301 = M00*M10 + M01*M11 + M02*M12;
    float c302 = M00*M20 + M01*M21 + M02*M22;
    float c311 = M10*M10 + M11*M11 + M12*M12;
    float c312 = M10*M20 + M11*M21 + M12*M22;
    float c322 = M20*M20 + M21*M21 + M22*M22;

    float X = tx, Y = ty, Z = tz;
    float valid = (Z > 0.2f) ? 1.0f : 0.0f;
    float Zc = fmaxf(Z, 0.2f);
    float mx = FXc*X/Zc + CXc;
    float my = FYc*Y/Zc + CYc;
    float j00 = FXc/Zc;
    float j02 = -FXc*X/(Zc*Zc);
    float j11 = FYc/Zc;
    float j12 = -FYc*Y/(Zc*Zc);

    float u0 = j00*c300 + j02*c302;
    float u1 = j00*c301 + j02*c312;
    float u2 = j00*c302 + j02*c322;
    float v1 = j11*c311 + j12*c312;
    float v2 = j11*c312 + j12*c322;
    float cA = u0*j00 + u2*j02 + 0.3f;
    float cB = u1*j11 + u2*j12;
    float cC = v1*j11 + v2*j12 + 0.3f;
    float det = fmaxf(cA*cC - cB*cB, EPSf);
    float invd = 1.0f/det;

    h1s[f]   = make_float4(mx, my, -0.5f*cC*invd, cB*invd);
    pCs[f]   = -0.5f*cA*invd;
    colds[f] = make_float4(expf(lop[f]) * valid, cols[3*f+0], cols[3*f+1], cols[3*f+2]);
    // exact: max_dx p(dx,dy) = -dy^2/(2*cC)  (det identity holds: cA*cC-cB^2 >= 0.09 > eps)
    // so |dy| >= 6*sqrt(cC)  =>  p < -18 for the whole row
    rys[f]   = 6.0f*sqrtf(cC);

    // stable bitonic sort on (Zc_bits << 32 | idx); Zc > 0 so float bits
    // are order-isomorphic as uint; idx makes it stable (== jnp.argsort).
    int t = f;
    unsigned long long key =
        ((unsigned long long)__float_as_uint(Zc) << 32) | (unsigned int)t;
    __syncthreads();

    #pragma unroll
    for (int k = 2; k <= F_CNT; k <<= 1) {
        bool dir = ((t & k) == 0);
        int j = k >> 1;
        for (; j >= 32; j >>= 1) {
            sk[t] = key;
            __syncthreads();
            unsigned long long other = sk[t ^ j];
            bool takeMin = (dir == ((t & j) == 0));
            key = ((key < other) == takeMin) ? key : other;
            __syncthreads();
        }
        for (; j >= 1; j >>= 1) {
            unsigned long long other = __shfl_xor_sync(0xffffffffu, key, j);
            bool takeMin = (dir == ((t & j) == 0));
            key = ((key < other) == takeMin) ? key : other;
        }
    }

    int s = (int)(key & 0xffffffffu);
    g_sh1[t]   = h1s[s];
    g_spC[t]   = pCs[s];
    g_scold[t] = colds[s];
    g_smyry[t] = make_float2(h1s[s].y, rys[s]);
}

// ============ render: 512 thr = 64 slots x 8 segs, 2 px/thread (same row) ============
// Block b owns two 64-px row-runs: run = b and run = b+288 (rows differ by 96
// => balanced central/edge work). px = 64*run + lane (+32 for second pixel).
__global__ void __launch_bounds__(512, 2) render_kernel(
        float* __restrict__ out,
        const float* __restrict__ img,
        const float* __restrict__ mask)
{
    // sh1 region (16 KB) is re-used as comb[8][128] after the render loop
    __shared__ __align__(16) char smem_raw[16384];
    float4* sh1 = (float4*)smem_raw;                // [1024]
    float4 (*comb)[128] = (float4(*)[128])smem_raw; // [8][128] alias
    __shared__ float  spC[F_CNT];
    __shared__ float4 scold[F_CNT];
    __shared__ float2 smyry[F_CNT];
    __shared__ float  red[128];
    __shared__ int s_last;

    int tid = threadIdx.x;
    // load sorted attrs (1024 entries, 512 threads)
    #pragma unroll
    for (int i = tid; i < F_CNT; i += 512) {
        sh1[i]   = g_sh1[i];
        spC[i]   = g_spC[i];
        scold[i] = g_scold[i];
        smyry[i] = g_smyry[i];
    }
    __syncthreads();

    int pl   = tid & 63;            // pixel slot
    int seg  = tid >> 6;            // depth segment 0..7
    int lane = pl & 31;
    int chunk = pl >> 5;            // 0/1
    int run  = blockIdx.x + NRBLK * chunk;      // 0..575 (64-px runs)
    int row  = run / 3;
    float fy  = (float)row;
    float fx0 = (float)((run % 3) * 64 + lane);
    float fx1 = fx0 + 32.0f;

    int base = seg * GSEG;
    float T0 = 1.0f, r0a = 0.0f, g0a = 0.0f, b0a = 0.0f;
    float T1 = 1.0f, r1a = 0.0f, g1a = 0.0f, b1a = 0.0f;
#pragma unroll 4
    for (int i = base; i < base + GSEG; i++) {
        float2 yr = smyry[i];
        float dy = fy - yr.x;
        if (fabsf(dy) < yr.y) {                  // warp-uniform row test
            float4 h = sh1[i];
            float pc = spC[i];
            float sB = h.w * dy;                 // pB*dy
            float s2 = pc * dy * dy;             // pC*dy^2
            float dx0 = fx0 - h.x;
            float dx1 = fx1 - h.x;
            float p0 = fmaf(fmaf(h.z, dx0, sB), dx0, s2);
            float p1 = fmaf(fmaf(h.z, dx1, sB), dx1, s2);
            if (fmaxf(p0, p1) > -18.0f) {        // both alphas < 1.6e-8: skip
                float4 c = scold[i];
                float al0 = fminf(c.x * __expf(fminf(p0, 0.0f)), 0.99f);
                float al1 = fminf(c.x * __expf(fminf(p1, 0.0f)), 0.99f);
                float w0 = al0 * T0, w1 = al1 * T1;
                r0a = fmaf(w0, c.y, r0a);  r1a = fmaf(w1, c.y, r1a);
                g0a = fmaf(w0, c.z, g0a);  g1a = fmaf(w1, c.z, g1a);
                b0a = fmaf(w0, c.w, b0a);  b1a = fmaf(w1, c.w, b1a);
                T0 *= (1.0f - al0);        T1 *= (1.0f - al1);
            }
        }
    }
    __syncthreads();                 // all sh1 reads done before comb aliases it
    comb[seg][pl]      = make_float4(T0, r0a, g0a, b0a);
    comb[seg][pl + 64] = make_float4(T1, r1a, g1a, b1a);
    __syncthreads();

    // ---- per-pixel ordered fold of 8 segments (threads 0..127) ----
    if (tid < 128) {
        float Tt = 1.0f, r = 0.0f, g = 0.0f, b = 0.0f;
#pragma unroll
        for (int s = 0; s < SEG; s++) {
            float4 vv = comb[s][tid];
            r = fmaf(Tt, vv.y, r);
            g = fmaf(Tt, vv.z, g);
            b = fmaf(Tt, vv.w, b);
            Tt *= vv.x;
        }
        float o0 = r + Tt, o1 = g + Tt, o2 = b + Tt;  // 1 - sum(w) == prod(1-alpha)
        // slot = (pl & 63) + 64*half ; px = 64*run + lane + 32*half
        int sl    = tid & 63;
        int half  = tid >> 6;
        int ch    = sl >> 5;
        int ln    = sl & 31;
        int rn    = blockIdx.x + NRBLK * ch;
        int p     = rn * 64 + ln + half * 32;
        out[p]          = o0;
        out[NPIX + p]   = o1;
        out[2*NPIX + p] = o2;

        float m  = mask[p];
        float bt = 1.0f - m;
        float d0 = o0 - fmaf(img[p],          m, bt);
        float d1 = o1 - fmaf(img[NPIX + p],   m, bt);
        float d2 = o2 - fmaf(img[2*NPIX + p], m, bt);
        red[tid] = fmaf(d0, d0, fmaf(d1, d1, d2*d2));
    }
    __syncthreads();
#pragma unroll
    for (int s = 64; s > 0; s >>= 1) {
        if (tid < s) red[tid] += red[tid + s];
        __syncthreads();
    }

    // ---- last block finishes loss (fixed-order => deterministic) + resets state ----
    if (tid == 0) {
        g_partial[blockIdx.x] = red[0];
        __threadfence();
        int ticket = atomicAdd(&g_count, 1);
        s_last = (ticket == NRBLK - 1);
    }
    __syncthreads();
    if (s_last && tid < 32) {
        __threadfence();
        float a = 0.0f;
        for (int i = tid; i < NRBLK; i += 32)
            a += *((volatile float*)&g_partial[i]);
#pragma unroll
        for (int o = 16; o > 0; o >>= 1)
            a += __shfl_down_sync(0xffffffffu, a, o);
        if (tid == 0) {
            out[3 * NPIX] = a / (float)(3 * NPIX);
            g_count = 0;             // reset for next graph replay
        }
    }
}

// ---------------- launch ----------------
extern "C" void kernel_launch(void* const* d_in, const int* in_sizes, int n_in,
                              void* d_out, int out_size)
{
    const float* img   = (const float*)d_in[0];
    const float* mask  = (const float*)d_in[1];
    const float* vp    = (const float*)d_in[2];
    const int*   faces = (const int*)  d_in[3];
    const float* qs    = (const float*)d_in[4];
    const float* ls    = (const float*)d_in[5];
    const float* cols  = (const float*)d_in[6];
    const float* lop   = (const float*)d_in[7];
    float* out = (float*)d_out;

    prep_sort_kernel<<<1, 1024>>>(vp, faces, qs, ls, cols, lop);
    render_kernel<<<NRBLK, 512>>>(out, img, mask);
}